// round 6
// baseline (speedup 1.0000x reference)
#include <cuda_runtime.h>
#include <cstdint>

#define KDIM   8192
#define TPB    256
#define EPT    32      // elements per thread
#define MAXC   100
#define MINC   20

__device__ __forceinline__ uint32_t fkey(float f) {
    uint32_t u = __float_as_uint(f);
    return (u & 0x80000000u) ? ~u : (u | 0x80000000u);
}

__global__ __launch_bounds__(TPB)
void retention_kernel(const float* __restrict__ logits,
                      float* __restrict__ bs_out,
                      float* __restrict__ cls_out,
                      float* __restrict__ mask_out)
{
    __shared__ uint32_t stage[KDIM];       // 32KB staging (swizzled)
    __shared__ int hist[256];
    __shared__ int warpTot[8];
    __shared__ int sel[MAXC];
    __shared__ int shCount;
    __shared__ unsigned int shPrefix;
    __shared__ int shKK;

    const int tid  = threadIdx.x;
    const int lane = tid & 31;
    const int warp = tid >> 5;
    const int row  = blockIdx.x;

    if (tid == 0) { shCount = 0; shPrefix = 0u; }
    __syncthreads();

    // ---- Phase 1: coalesced load, count(logit>=0), key transform, swizzled STS
    const float4* src = (const float4*)(logits + (size_t)row * KDIM);
    int c0 = 0;
    #pragma unroll
    for (int j = 0; j < 8; j++) {
        int v4 = tid + j * TPB;                 // float4 index 0..2047
        float4 v = src[v4];
        c0 += (v.x >= 0.f) + (v.y >= 0.f) + (v.z >= 0.f) + (v.w >= 0.f);
        uint4 kk;
        kk.x = fkey(v.x); kk.y = fkey(v.y); kk.z = fkey(v.z); kk.w = fkey(v.w);
        uint32_t a = (uint32_t)v4 * 16u;
        a ^= ((a >> 7) & 7u) << 4;              // 128B XOR swizzle
        *(uint4*)((char*)stage + a) = kk;
    }
    #pragma unroll
    for (int o = 16; o; o >>= 1) c0 += __shfl_xor_sync(0xffffffffu, c0, o);
    if (lane == 0) atomicAdd(&shCount, c0);
    __syncthreads();

    // ---- Phase 2: per-thread-contiguous readback into registers
    uint32_t key[EPT];
    #pragma unroll
    for (int j = 0; j < 8; j++) {
        uint32_t a = (uint32_t)tid * 128u + (uint32_t)j * 16u;
        a ^= ((a >> 7) & 7u) << 4;
        uint4 kk = *(const uint4*)((const char*)stage + a);
        key[j*4+0] = kk.x; key[j*4+1] = kk.y; key[j*4+2] = kk.z; key[j*4+3] = kk.w;
    }

    int numTrain = shCount;
    numTrain = min(max(numTrain, MINC), MAXC);
    if (tid == 0) shKK = numTrain;
    __syncthreads();

    // ---- Phase 3: 4-pass radix select (descending) for the numTrain-th largest
    #pragma unroll
    for (int pp = 0; pp < 4; pp++) {
        const int shift = 24 - 8 * pp;
        hist[tid] = 0;
        __syncthreads();
        const unsigned pref = shPrefix;
        const int kkCur = shKK;

        #pragma unroll
        for (int i = 0; i < EPT; i++) {
            uint32_t k = key[i];
            bool act = (pp == 0) || ((k >> (shift + 8)) == (pref >> (shift + 8)));
            unsigned active = __ballot_sync(0xffffffffu, act);
            if (act) {
                int bin = (int)((k >> shift) & 0xFFu);
                unsigned m = __match_any_sync(active, bin);
                int leader = __ffs(m) - 1;
                if (lane == leader) atomicAdd(&hist[bin], __popc(m));
            }
        }
        __syncthreads();

        // parallel suffix-sum over 256 bins, descending (d = 255 - tid)
        int d = 255 - tid;
        int h = hist[d];
        int inc = h;
        #pragma unroll
        for (int o = 1; o < 32; o <<= 1) {
            int n = __shfl_up_sync(0xffffffffu, inc, o);
            if (lane >= o) inc += n;
        }
        if (lane == 31) warpTot[warp] = inc;
        __syncthreads();
        int wOff = 0;
        #pragma unroll
        for (int w = 0; w < 8; w++) if (w < warp) wOff += warpTot[w];
        int suf = wOff + inc;           // count of elements in bins >= d
        int below = suf - h;            // count of elements in bins > d
        if (suf >= kkCur && below < kkCur) {
            shKK = kkCur - below;
            shPrefix = pref | ((unsigned)d << shift);
        }
        __syncthreads();
    }

    const uint32_t T  = shPrefix;   // exact key of the numTrain-th largest
    const int nEq     = shKK;       // how many ties at T to keep (lowest indices)

    // ---- Phase 4: ordered compaction (tid order == global index order)
    int cg = 0, ce = 0;
    #pragma unroll
    for (int i = 0; i < EPT; i++) {
        cg += (key[i] > T);
        ce += (key[i] == T);
    }
    int pack = (cg << 16) | ce;
    int inc2 = pack;
    #pragma unroll
    for (int o = 1; o < 32; o <<= 1) {
        int n = __shfl_up_sync(0xffffffffu, inc2, o);
        if (lane >= o) inc2 += n;
    }
    if (lane == 31) warpTot[warp] = inc2;
    __syncthreads();
    int wOff2 = 0;
    #pragma unroll
    for (int w = 0; w < 8; w++) if (w < warp) wOff2 += warpTot[w];
    int exc = wOff2 + inc2 - pack;
    int g = exc >> 16;
    int e = exc & 0xFFFF;

    #pragma unroll
    for (int i = 0; i < EPT; i++) {
        uint32_t k = key[i];
        if (k > T) {
            sel[g + min(e, nEq)] = tid * EPT + i;
            g++;
        } else if (k == T) {
            if (e < nEq) sel[g + e] = tid * EPT + i;
            e++;
        }
    }
    __syncthreads();

    // ---- Phase 5: emit as FLOAT32 (harness output buffer is float32:
    //      int bit patterns written in R1 produced NaN (-1 == 0xFFFFFFFF))
    if (tid < MAXC) {
        bool valid = tid < numTrain;
        size_t o = (size_t)row * MAXC + tid;
        bs_out[o]   = valid ? (float)row      : -1.0f;
        cls_out[o]  = valid ? (float)sel[tid] : -1.0f;
        mask_out[o] = valid ? 1.0f : 0.0f;
    }
}

extern "C" void kernel_launch(void* const* d_in, const int* in_sizes, int n_in,
                              void* d_out, int out_size) {
    const float* logits = (const float*)d_in[0];
    const int total = in_sizes[0];
    const int bs = total / KDIM;
    const size_t per = (size_t)bs * MAXC;

    // Output layout: [bs_idx | cls_idx | mask], each [bs, 100], float32.
    float* out = (float*)d_out;
    float* bs_out   = out;
    float* cls_out  = out + per;
    float* mask_out = out + 2 * per;

    retention_kernel<<<bs, TPB>>>(logits, bs_out, cls_out, mask_out);
}

// round 7
// speedup vs baseline: 1.6451x; 1.6451x over previous
#include <cuda_runtime.h>
#include <cstdint>

#define KDIM   8192
#define TPB    256
#define MAXC   100
#define MINC   20
#define CAP    1024

__device__ __forceinline__ uint32_t fkey(float f) {
    uint32_t u = __float_as_uint(f);
    // neg -> ~u, pos -> u | 0x80000000 (monotone order-preserving key)
    return u ^ (uint32_t)(((int32_t)u >> 31) | (int32_t)0x80000000);
}

__global__ __launch_bounds__(TPB, 4)
void retention_kernel(const float* __restrict__ logits,
                      float* __restrict__ bs_out,
                      float* __restrict__ cls_out,
                      float* __restrict__ mask_out)
{
    __shared__ uint32_t stage[KDIM];      // 32KB swizzled key staging
    __shared__ uint32_t cand[CAP];        // pass-0 survivors (keys only)
    __shared__ int hist[256];
    __shared__ int warpTot[8];
    __shared__ int sel[MAXC];
    __shared__ int shCount, shKK, shN, shBin;
    __shared__ unsigned shPrefix;

    const int tid  = threadIdx.x;
    const int lane = tid & 31;
    const int warp = tid >> 5;
    const int row  = blockIdx.x;

    hist[tid] = 0;
    if (tid == 0) { shCount = 0; shPrefix = 0u; shN = 0; }
    __syncthreads();

    // ---- Phase 1: load + count(>=0) + key + swizzled STS + fused top-byte histogram
    const float4* src = (const float4*)(logits + (size_t)row * KDIM);
    int c0 = 0;
    #pragma unroll
    for (int j = 0; j < 8; j++) {
        int v4 = tid + j * TPB;
        float4 v = src[v4];
        c0 += (v.x >= 0.f) + (v.y >= 0.f) + (v.z >= 0.f) + (v.w >= 0.f);
        uint4 kk;
        kk.x = fkey(v.x); kk.y = fkey(v.y); kk.z = fkey(v.z); kk.w = fkey(v.w);
        uint32_t a = (uint32_t)v4 * 16u;
        a ^= ((a >> 7) & 7u) << 4;                  // 128B XOR swizzle
        *(uint4*)((char*)stage + a) = kk;
        #pragma unroll
        for (int c = 0; c < 4; c++) {
            uint32_t k = (c == 0) ? kk.x : (c == 1) ? kk.y : (c == 2) ? kk.z : kk.w;
            int bin = (int)(k >> 24);
            unsigned m = __match_any_sync(0xffffffffu, bin);
            if ((__ffs(m) - 1) == lane) atomicAdd(&hist[bin], __popc(m));
        }
    }
    #pragma unroll
    for (int o = 16; o; o >>= 1) c0 += __shfl_xor_sync(0xffffffffu, c0, o);
    if (lane == 0) atomicAdd(&shCount, c0);
    __syncthreads();

    const int numTrain = min(max(shCount, MINC), MAXC);
    if (tid == 0) shKK = numTrain;
    __syncthreads();

    // ---- Phase 2: 4-level radix select; levels 1-3 run over compacted candidates
    const uint32_t* arr = stage;
    int L = KDIM;

    #pragma unroll 1
    for (int pp = 0; pp < 4; pp++) {
        const int shift = 24 - 8 * pp;
        if (pp > 0) {
            hist[tid] = 0;
            __syncthreads();
            const unsigned prefHi = shPrefix >> (shift + 8);
            for (int i = tid; i < L; i += TPB) {
                uint32_t k = arr[i];
                if ((k >> (shift + 8)) == prefHi)
                    atomicAdd(&hist[(k >> shift) & 255u], 1);
            }
            __syncthreads();
        }
        const unsigned pref = shPrefix;
        const int kkCur = shKK;

        // suffix scan over 256 bins, descending digit d = 255 - tid
        int d = 255 - tid;
        int h = hist[d];
        int inc = h;
        #pragma unroll
        for (int o = 1; o < 32; o <<= 1) {
            int t = __shfl_up_sync(0xffffffffu, inc, o);
            if (lane >= o) inc += t;
        }
        if (lane == 31) warpTot[warp] = inc;
        __syncthreads();
        int wOff = 0;
        #pragma unroll
        for (int w = 0; w < 8; w++) if (w < warp) wOff += warpTot[w];
        int suf = wOff + inc;            // count in bins >= d
        int below = suf - h;             // count in bins > d
        if (suf >= kkCur && below < kkCur) {
            shKK = kkCur - below;
            shPrefix = pref | ((unsigned)d << shift);
            shBin = h;                   // survivors in the crossing bin
        }
        __syncthreads();

        if (pp == 0) {
            int n = shBin;
            if (n <= CAP) {              // typical: n ~ 5-200
                const unsigned d0 = shPrefix >> 24;
                #pragma unroll
                for (int j = 0; j < 8; j++) {
                    uint32_t a = (uint32_t)tid * 128u + (uint32_t)j * 16u;
                    a ^= ((a >> 7) & 7u) << 4;
                    uint4 kk = *(const uint4*)((const char*)stage + a);
                    if ((kk.x >> 24) == d0) cand[atomicAdd(&shN, 1)] = kk.x;
                    if ((kk.y >> 24) == d0) cand[atomicAdd(&shN, 1)] = kk.y;
                    if ((kk.z >> 24) == d0) cand[atomicAdd(&shN, 1)] = kk.z;
                    if ((kk.w >> 24) == d0) cand[atomicAdd(&shN, 1)] = kk.w;
                }
                arr = cand;
                L = n;
                __syncthreads();
            }                            // else: fall back to full stage sweeps
        }
    }

    const uint32_t T  = shPrefix;        // exact key of the numTrain-th largest
    const int nEq     = shKK;            // ties at T to keep (lowest indices)

    // ---- Phase 3: ordered compaction (thread-contiguous stage order == index order)
    int cg = 0, ce = 0;
    #pragma unroll
    for (int j = 0; j < 8; j++) {
        uint32_t a = (uint32_t)tid * 128u + (uint32_t)j * 16u;
        a ^= ((a >> 7) & 7u) << 4;
        uint4 kk = *(const uint4*)((const char*)stage + a);
        cg += (kk.x > T) + (kk.y > T) + (kk.z > T) + (kk.w > T);
        ce += (kk.x == T) + (kk.y == T) + (kk.z == T) + (kk.w == T);
    }
    int pack = (cg << 16) | ce;
    int inc2 = pack;
    #pragma unroll
    for (int o = 1; o < 32; o <<= 1) {
        int t = __shfl_up_sync(0xffffffffu, inc2, o);
        if (lane >= o) inc2 += t;
    }
    if (lane == 31) warpTot[warp] = inc2;
    __syncthreads();
    int wOff2 = 0;
    #pragma unroll
    for (int w = 0; w < 8; w++) if (w < warp) wOff2 += warpTot[w];
    int exc = wOff2 + inc2 - pack;
    int g = exc >> 16;
    int e = exc & 0xFFFF;

    #pragma unroll
    for (int j = 0; j < 8; j++) {
        uint32_t a = (uint32_t)tid * 128u + (uint32_t)j * 16u;
        a ^= ((a >> 7) & 7u) << 4;
        uint4 kk = *(const uint4*)((const char*)stage + a);
        #pragma unroll
        for (int c = 0; c < 4; c++) {
            uint32_t k = (c == 0) ? kk.x : (c == 1) ? kk.y : (c == 2) ? kk.z : kk.w;
            int idx = tid * 32 + j * 4 + c;
            if (k > T) {
                sel[g + min(e, nEq)] = idx;
                g++;
            } else if (k == T) {
                if (e < nEq) sel[g + e] = idx;
                e++;
            }
        }
    }
    __syncthreads();

    // ---- Phase 4: emit float32 [bs_idx | cls_idx | mask]
    if (tid < MAXC) {
        bool valid = tid < numTrain;
        size_t o = (size_t)row * MAXC + tid;
        bs_out[o]   = valid ? (float)row      : -1.0f;
        cls_out[o]  = valid ? (float)sel[tid] : -1.0f;
        mask_out[o] = valid ? 1.0f : 0.0f;
    }
}

extern "C" void kernel_launch(void* const* d_in, const int* in_sizes, int n_in,
                              void* d_out, int out_size) {
    const float* logits = (const float*)d_in[0];
    const int total = in_sizes[0];
    const int bs = total / KDIM;
    const size_t per = (size_t)bs * MAXC;

    float* out = (float*)d_out;
    float* bs_out   = out;
    float* cls_out  = out + per;
    float* mask_out = out + 2 * per;

    retention_kernel<<<bs, TPB>>>(logits, bs_out, cls_out, mask_out);
}